// round 13
// baseline (speedup 1.0000x reference)
#include <cuda_runtime.h>
#include <cstdint>

#define N 2304
#define BB 1024
#define FF 32
#define TEAM 144
#define NCTA (2 * TEAM)
#define NTHR 512
#define RPC 16                     // rows (fwd) / cols (bwd) per CTA

#define CPS 9                      // chunks per step
#define CW 256                     // chunk extent along streamed dim
#define SLOT_FLOATS (RPC * CW)     // 4096 floats = 16 KB
#define RING 5
#define DEPTH 4
#define TOTAL (31 * CPS)           // 279
#define SMEM_BYTES ((RING * SLOT_FLOATS + N + 16 * 33 + 32) * 4)   // ~93 KB

// device scratch (no allocation allowed)
__device__ float g_v[FF * N];
__device__ float g_z[FF * N];
__device__ float g_keep[FF * N];
__device__ float g_vsum[TEAM];
__device__ int   g_cntF[64];
__device__ int   g_cntB[64];
__device__ int   g_cntAll;

__global__ void setup_kernel(const int* __restrict__ sel) {
    int tid = threadIdx.x;
    for (int i = tid; i < FF * N; i += NTHR) g_keep[i] = 1.0f;
    if (tid < 64) { g_cntF[tid] = 0; g_cntB[tid] = 0; }
    if (tid == 64) g_cntAll = 0;
    __syncthreads();
    if (tid < 256) {
        int f = sel[3 * tid];
        int node = sel[3 * tid + 1] * 64 + sel[3 * tid + 2];
        g_keep[f * N + node] = 0.0f;
    }
}

__device__ __forceinline__ void teambar(int* cnt, int s) {
    __threadfence();
    __syncthreads();
    if (threadIdx.x == 0) {
        atomicAdd(&cnt[s], 1);
        volatile int* c = &cnt[s];
        while (*c < TEAM) { }
        __threadfence();
    }
    __syncthreads();
}

__device__ __forceinline__ void cpasync16(uint32_t dst, const void* src) {
    asm volatile("cp.async.cg.shared.global [%0], [%1], 16;" :: "r"(dst), "l"(src));
}
__device__ __forceinline__ void cpcommit() { asm volatile("cp.async.commit_group;"); }
__device__ __forceinline__ void cpwait3()  { asm volatile("cp.async.wait_group 3;" ::: "memory"); }
__device__ __forceinline__ void cpwait0()  { asm volatile("cp.async.wait_group 0;" ::: "memory"); }

// Persistent solver + fused final. 288 CTAs = 2/SM (one per team per SM):
// while one CTA waits at its team barrier, the co-resident CTA keeps streaming.
// CTAs 0..143:   forward  v_f = keep_f * (b_f + W[f-1] @ v_{f-1})   (16 rows each)
// CTAs 144..287: backward z_f = 1 + W[f]^T @ (keep_{f+1} * z_{f+1}) (16 cols each)
__global__ void __launch_bounds__(NTHR, 2)
solve_kernel(const float* __restrict__ W, const float* __restrict__ B,
             const int* __restrict__ cand, float* __restrict__ out)
{
    extern __shared__ float smem[];
    float* s_slot = smem;                       // RING x 4096 floats
    float* s_v    = smem + RING * SLOT_FLOATS;  // N
    float* s_red  = s_v + N;                    // 16x33 + spill

    uint32_t sbase;
    asm("{ .reg .u64 t; cvta.to.shared.u64 t, %1; cvt.u32.u64 %0, t; }" : "=r"(sbase) : "l"(smem));

    int tid = threadIdx.x;
    int cta = blockIdx.x;
    int warp = tid >> 5, lane = tid & 31;       // 16 warps

    if (cta < TEAM) {
        // ================= FORWARD TEAM =================
        int r0 = cta * RPC;
        float myacc = 0.f;

        // chunk idx -> slab ff = idx/9 (W[ff] used by step f=ff+1), col block cc
        auto issue = [&](int idx) {
            int ff = idx / CPS, cc = idx - ff * CPS;
            const float* base = W + ((size_t)ff * N + r0) * N + cc * CW;
            uint32_t dst = sbase + (uint32_t)(idx % RING) * (SLOT_FLOATS * 4);
            #pragma unroll
            for (int k = 0; k < 2; ++k) {
                int e = tid + k * NTHR;          // e = row*64 + q (row<16, q<64)
                int row = e >> 6, q = e & 63;
                cpasync16(dst + (uint32_t)e * 16, base + (size_t)row * N + q * 4);
            }
            cpcommit();
        };

        int issued = 0;
        #pragma unroll
        for (int i = 0; i < DEPTH; ++i) issue(issued++);

        if (tid < RPC) {
            int row = r0 + tid;
            float v = g_keep[row] * B[row];
            g_v[row] = v;
            myacc += v;
        }
        teambar(g_cntF, 0);

        for (int f = 1; f < FF; ++f) {
            for (int n = tid; n < N; n += NTHR) s_v[n] = g_v[(f - 1) * N + n];

            float acc = 0.f;
            int g0 = (f - 1) * CPS;
            #pragma unroll
            for (int c = 0; c < CPS; ++c) {
                if (issued < TOTAL) cpwait3(); else cpwait0();
                __syncthreads();                 // chunk g0+c visible; slot reuse safe
                if (issued < TOTAL) issue(issued++);

                const float4* wrow = (const float4*)(s_slot + ((g0 + c) % RING) * SLOT_FLOATS + warp * CW);
                const float4* vv   = (const float4*)(s_v + c * CW);
                float4 w0 = wrow[lane],      v0 = vv[lane];
                float4 w1 = wrow[lane + 32], v1 = vv[lane + 32];
                acc += w0.x * v0.x + w0.y * v0.y + w0.z * v0.z + w0.w * v0.w;
                acc += w1.x * v1.x + w1.y * v1.y + w1.z * v1.z + w1.w * v1.w;
            }
            #pragma unroll
            for (int o = 16; o; o >>= 1)
                acc += __shfl_xor_sync(0xffffffffu, acc, o);
            int ra = r0 + warp;                  // warp owns one row
            if (lane == 0) {
                float va = g_keep[f * N + ra] * (B[f * N + ra] + acc);
                g_v[f * N + ra] = va;
                myacc += va;
            }
            if (f < FF - 1) teambar(g_cntF, f);
        }

        #pragma unroll
        for (int o = 16; o; o >>= 1) myacc += __shfl_xor_sync(0xffffffffu, myacc, o);
        if (lane == 0) s_red[warp] = myacc;
        __syncthreads();
        if (tid == 0) {
            float t = 0.f;
            #pragma unroll
            for (int w = 0; w < 16; ++w) t += s_red[w];
            g_vsum[cta] = t;
        }
    } else {
        // ================= BACKWARD TEAM =================
        int id = cta - TEAM;
        int c0 = id * RPC;

        // chunk idx -> slab ff = 30 - idx/9 (step computes z_ff), row block cc
        auto issue = [&](int idx) {
            int ff = 30 - idx / CPS, cc = idx - (30 - ff) * CPS;
            const float* base = W + ((size_t)ff * N + cc * CW) * N + c0;
            uint32_t dst = sbase + (uint32_t)(idx % RING) * (SLOT_FLOATS * 4);
            #pragma unroll
            for (int k = 0; k < 2; ++k) {
                int e = tid + k * NTHR;          // e = row*4 + part (row<256, part<4)
                int row = e >> 2, part = e & 3;
                cpasync16(dst + (uint32_t)e * 16, base + (size_t)row * N + part * 4);
            }
            cpcommit();
        };

        int issued = 0;
        #pragma unroll
        for (int i = 0; i < DEPTH; ++i) issue(issued++);

        if (tid < RPC) g_z[31 * N + c0 + tid] = 1.0f;
        teambar(g_cntB, 0);

        for (int f = FF - 2; f >= 0; --f) {
            for (int n = tid; n < N; n += NTHR)
                s_v[n] = g_keep[(f + 1) * N + n] * g_z[(f + 1) * N + n];

            int tx = tid & 15, ty = tid >> 4;    // 16 cols x 32 row-lanes
            float p = 0.f;
            int g0 = (30 - f) * CPS;
            #pragma unroll
            for (int c = 0; c < CPS; ++c) {
                if (issued < TOTAL) cpwait3(); else cpwait0();
                __syncthreads();
                if (issued < TOTAL) issue(issued++);

                const float* sw = s_slot + ((g0 + c) % RING) * SLOT_FLOATS;
                const float* vv = s_v + c * CW;
                #pragma unroll
                for (int j = 0; j < 8; ++j) {    // row r = ty + 32*j within chunk
                    int r = ty + j * 32;
                    p += sw[r * RPC + tx] * vv[r];
                }
            }
            __syncthreads();                     // done with slots this step ordering
            s_red[tx * 33 + ty] = p;             // padded transpose
            __syncthreads();
            if (warp < RPC) {                    // warp w reduces col c0+w
                float q = s_red[warp * 33 + lane];
                #pragma unroll
                for (int o = 16; o; o >>= 1)
                    q += __shfl_xor_sync(0xffffffffu, q, o);
                if (lane == 0) g_z[f * N + c0 + warp] = 1.0f + q;
            }
            if (f > 0) teambar(g_cntB, 31 - f);
        }
    }

    // ================= FUSED FINAL =================
    __threadfence();
    __syncthreads();
    if (tid == 0) atomicAdd(&g_cntAll, 1);
    if (cta == 0) {
        if (tid == 0) {
            volatile int* c = &g_cntAll;
            while (*c < NCTA) { }
            __threadfence();
        }
        __syncthreads();
        float t = (tid < TEAM) ? g_vsum[tid] : 0.f;
        #pragma unroll
        for (int o = 16; o; o >>= 1) t += __shfl_xor_sync(0xffffffffu, t, o);
        if (lane == 0) s_red[warp] = t;
        __syncthreads();
        if (tid == 0) {
            float tt = 0.f;
            #pragma unroll
            for (int w = 0; w < 16; ++w) tt += s_red[w];
            s_red[0] = tt;
        }
        __syncthreads();
        float TOT = s_red[0];
        for (int b = tid; b < BB; b += NTHR) {
            int cf = cand[3 * b];
            int cn = cand[3 * b + 1] * 64 + cand[3 * b + 2];
            out[b] = TOT - g_v[cf * N + cn] * g_z[cf * N + cn];
        }
    }
}

extern "C" void kernel_launch(void* const* d_in, const int* in_sizes, int n_in,
                              void* d_out, int out_size) {
    const float* weights = (const float*)d_in[0];
    const float* biases  = (const float*)d_in[1];
    const int*   sel     = (const int*)d_in[2];
    const int*   cand    = (const int*)d_in[3];
    float*       out     = (float*)d_out;

    cudaFuncSetAttribute(solve_kernel, cudaFuncAttributeMaxDynamicSharedMemorySize, SMEM_BYTES);

    setup_kernel<<<1, NTHR>>>(sel);
    solve_kernel<<<NCTA, NTHR, SMEM_BYTES>>>(weights, biases, cand, out);
}